// round 6
// baseline (speedup 1.0000x reference)
#include <cuda_runtime.h>
#include <cuda_bf16.h>
#include <math.h>
#include <stdint.h>

#define N_NODES   50000
#define N_EDGES   600000
#define IN_DIM    64
#define D         128
#define N_LAYERS  8
#define N_ETYPES  44
#define N_MENTIONS 100000
#define N_VARS    20000
#define OUT_DIM   100

// ---------------- scratch ----------------
__device__ float g_h[N_NODES * D];
__device__ float g_t[N_NODES * D];
__device__ float g_acc[N_NODES * D];
__device__ float g_PQ[N_NODES * 512];
__device__ float g_R[N_LAYERS * N_ETYPES * 256];
__device__ float g_vsum[N_VARS * D];
__device__ float g_vcnt[N_VARS];
__device__ float g_vrep[N_VARS * D];

// ---------------- helpers ----------------
__device__ __forceinline__ uint32_t smem_u32(const void* p) {
    uint32_t a;
    asm("{ .reg .u64 t; cvta.to.shared.u64 t, %1; cvt.u32.u64 %0, t; }" : "=r"(a) : "l"(p));
    return a;
}
__device__ __forceinline__ void ldsm4(uint32_t& r0, uint32_t& r1, uint32_t& r2, uint32_t& r3, uint32_t addr) {
    asm volatile("ldmatrix.sync.aligned.m8n8.x4.shared.b16 {%0,%1,%2,%3}, [%4];"
                 : "=r"(r0), "=r"(r1), "=r"(r2), "=r"(r3) : "r"(addr));
}
__device__ __forceinline__ void mma_bf16(float* c, uint32_t a0, uint32_t a1, uint32_t a2, uint32_t a3,
                                         uint32_t b0, uint32_t b1) {
    asm volatile("mma.sync.aligned.m16n8k16.row.col.f32.bf16.bf16.f32 "
                 "{%0,%1,%2,%3}, {%4,%5,%6,%7}, {%8,%9}, {%0,%1,%2,%3};"
                 : "+f"(c[0]), "+f"(c[1]), "+f"(c[2]), "+f"(c[3])
                 : "r"(a0), "r"(a1), "r"(a2), "r"(a3), "r"(b0), "r"(b1));
}

// ---------------- generic tiled SGEMM ----------------
__global__ void sgemm_kernel(const float* __restrict__ A, int lda,
                             const float* __restrict__ B, int ldb,
                             const float* __restrict__ bias,
                             float* __restrict__ C, int ldc,
                             int M, int N, int K, int act)
{
    __shared__ __align__(16) float As[16][68];
    __shared__ __align__(16) float Bs[16][64];
    const int tid = threadIdx.x;
    const int m0 = blockIdx.y * 64, n0 = blockIdx.x * 64;
    const int ty = tid >> 4, tx = tid & 15;

    float acc[4][4];
#pragma unroll
    for (int i = 0; i < 4; i++)
#pragma unroll
        for (int j = 0; j < 4; j++) acc[i][j] = 0.f;

    for (int k0 = 0; k0 < K; k0 += 16) {
        {
            int r = tid >> 4, c = tid & 15;
#pragma unroll
            for (int p = 0; p < 4; p++) {
                int m = m0 + p * 16 + r;
                As[c][p * 16 + r] = (m < M) ? A[(size_t)m * lda + k0 + c] : 0.f;
            }
        }
        {
            int r = tid >> 6, c = tid & 63;
#pragma unroll
            for (int p = 0; p < 4; p++) {
                int k = k0 + p * 4 + r, n = n0 + c;
                Bs[p * 4 + r][c] = (n < N) ? B[(size_t)k * ldb + n] : 0.f;
            }
        }
        __syncthreads();
#pragma unroll
        for (int kk = 0; kk < 16; kk++) {
            float4 a4 = *(const float4*)&As[kk][ty * 4];
            float4 b4 = *(const float4*)&Bs[kk][tx * 4];
            acc[0][0] += a4.x * b4.x; acc[0][1] += a4.x * b4.y; acc[0][2] += a4.x * b4.z; acc[0][3] += a4.x * b4.w;
            acc[1][0] += a4.y * b4.x; acc[1][1] += a4.y * b4.y; acc[1][2] += a4.y * b4.z; acc[1][3] += a4.y * b4.w;
            acc[2][0] += a4.z * b4.x; acc[2][1] += a4.z * b4.y; acc[2][2] += a4.z * b4.z; acc[2][3] += a4.z * b4.w;
            acc[3][0] += a4.w * b4.x; acc[3][1] += a4.w * b4.y; acc[3][2] += a4.w * b4.z; acc[3][3] += a4.w * b4.w;
        }
        __syncthreads();
    }
#pragma unroll
    for (int i = 0; i < 4; i++) {
        int m = m0 + ty * 4 + i;
        if (m >= M) continue;
#pragma unroll
        for (int j = 0; j < 4; j++) {
            int n = n0 + tx * 4 + j;
            if (n >= N) continue;
            float v = acc[i][j] + (bias ? bias[n] : 0.f);
            if (act == 1) v = fmaxf(v, 0.f);
            C[(size_t)m * ldc + n] = v;
        }
    }
}

// ---------------- per-etype R table ----------------
__global__ void r_kernel(const float* __restrict__ edge_emb,
                         const float* __restrict__ mlp_W1,
                         const float* __restrict__ mlp_b1,
                         float* __restrict__ R)
{
    int l = blockIdx.y, e = blockIdx.x, j = threadIdx.x;
    __shared__ float emb[128];
    if (j < 128) emb[j] = edge_emb[(l * N_ETYPES + e) * 128 + j];
    __syncthreads();
    const float* W = mlp_W1 + ((size_t)l * 384 + 256) * 256;
    float s = mlp_b1[l * 256 + j];
#pragma unroll 8
    for (int k = 0; k < 128; k++) s += emb[k] * W[k * 256 + j];
    R[((size_t)l * N_ETYPES + e) * 256 + j] = s;
}

// ---------------- mma.sync bf16x3 edge kernel ----------------
// Per 128-edge tile: D[128,128] = Z[128,256] @ W2, K in 2 chunks of 128.
// SMEM: W2^T [n][k] bf16 hi/lo resident (row stride 264 bf16 = 528B),
//       Z chunk [128][k128] bf16 hi/lo (row stride 136 bf16 = 272B).
#define ZH_OFF  0
#define ZL_OFF  34816
#define WH_OFF  69632
#define WL_OFF  137216
#define EDGE_SMEM_BYTES 204800
#define ZSTR 272
#define WSTR 528

__global__ __launch_bounds__(512, 1)
void edge_kernel(const int* __restrict__ edges,
                 const int* __restrict__ elab,
                 const float* __restrict__ Rl,    // [44][256]
                 const float* __restrict__ W2l,   // [256][128]
                 const float* __restrict__ b2l)   // [128]
{
    extern __shared__ __align__(16) char sm[];
    const uint32_t smb = smem_u32(sm);
    __shared__ int s_dst[128], s_src[128], s_lab[128];
    __shared__ float b2s[128];

    const int tid = threadIdx.x;
    const int wid = tid >> 5, lid = tid & 31;

    // stage W2^T hi/lo: row n (128 rows), k contiguous (256), stride 264 bf16
    for (int i = tid; i < 256 * 128; i += 512) {
        int k = i >> 7, n = i & 127;
        float w = W2l[i];
        __nv_bfloat16 hb = __float2bfloat16_rn(w);
        __nv_bfloat16 lb = __float2bfloat16_rn(w - __bfloat162float(hb));
        *(unsigned short*)(sm + WH_OFF + n * WSTR + k * 2) = __bfloat16_as_ushort(hb);
        *(unsigned short*)(sm + WL_OFF + n * WSTR + k * 2) = __bfloat16_as_ushort(lb);
    }
    if (tid < 128) b2s[tid] = b2l[tid];

    // producer mapping: 4 threads per edge row; thread covers 32 k-values
    const int pe = tid >> 2, pq = tid & 3;

    // ldmatrix lane addressing (constant parts)
    const int m_base = (wid & 3) * 32;
    const int n0 = (wid >> 2) * 32;
    // A: row = m_base + fm*16 + (lid&15); col byte = ((lid&16)?16:0) + ks*32
    const uint32_t aRow0 = (uint32_t)(m_base + (lid & 15)) * ZSTR + ((lid & 16) ? 16u : 0u);
    const uint32_t aRow1 = aRow0 + 16u * ZSTR;
    // B: row = n0 + (lid&7) + ((lid&16)?8:0) (+16 for second pair); col byte = ((lid&8)?16:0)
    const uint32_t bRow0 = (uint32_t)(n0 + (lid & 7) + ((lid & 16) ? 8 : 0)) * WSTR + ((lid & 8) ? 16u : 0u);
    const uint32_t bRow1 = bRow0 + 16u * WSTR;

    const int NT = (N_EDGES + 127) / 128;

    for (int tile = blockIdx.x; tile < NT; tile += gridDim.x) {
        const int base = tile * 128;
        if (tid < 128) {
            int eg = base + tid;
            bool v = eg < N_EDGES;
            s_dst[tid] = v ? edges[N_EDGES + eg] : 0;
            s_src[tid] = v ? edges[eg] : 0;
            s_lab[tid] = v ? elab[eg] : 0;
        }
        __syncthreads();

        const bool evalid = (base + pe) < N_EDGES;
        const int dn = s_dst[pe], sn = s_src[pe], lb = s_lab[pe];

        float cf[2][4][4];
#pragma unroll
        for (int fm = 0; fm < 2; fm++)
#pragma unroll
            for (int nf = 0; nf < 4; nf++)
#pragma unroll
                for (int r = 0; r < 4; r++) cf[fm][nf][r] = 0.f;

        for (int c = 0; c < 2; c++) {
            // ---- produce Z chunk: k in [c*128, c*128+128), this thread covers pq*32..+32 ----
            {
                char* Zh = sm + ZH_OFF + pe * ZSTR + pq * 64;
                char* Zl = sm + ZL_OFF + pe * ZSTR + pq * 64;
                if (evalid) {
                    const int kc = c * 128 + pq * 32;
                    const float* Pp = g_PQ + (size_t)dn * 512 + kc;
                    const float* Qp = g_PQ + (size_t)sn * 512 + 256 + kc;
                    const float* Rp = Rl + lb * 256 + kc;
#pragma unroll
                    for (int j = 0; j < 32; j += 4) {
                        float4 p4 = *(const float4*)(Pp + j);
                        float4 q4 = *(const float4*)(Qp + j);
                        float4 r4 = *(const float4*)(Rp + j);
                        float z0 = fmaxf(p4.x + q4.x + r4.x, 0.f);
                        float z1 = fmaxf(p4.y + q4.y + r4.y, 0.f);
                        float z2 = fmaxf(p4.z + q4.z + r4.z, 0.f);
                        float z3 = fmaxf(p4.w + q4.w + r4.w, 0.f);
                        __nv_bfloat16 h0 = __float2bfloat16_rn(z0), h1 = __float2bfloat16_rn(z1);
                        __nv_bfloat16 h2 = __float2bfloat16_rn(z2), h3 = __float2bfloat16_rn(z3);
                        __nv_bfloat16 l0 = __float2bfloat16_rn(z0 - __bfloat162float(h0));
                        __nv_bfloat16 l1 = __float2bfloat16_rn(z1 - __bfloat162float(h1));
                        __nv_bfloat16 l2 = __float2bfloat16_rn(z2 - __bfloat162float(h2));
                        __nv_bfloat16 l3 = __float2bfloat16_rn(z3 - __bfloat162float(h3));
                        *(uint32_t*)(Zh + j * 2)     = (uint32_t)__bfloat16_as_ushort(h0) | ((uint32_t)__bfloat16_as_ushort(h1) << 16);
                        *(uint32_t*)(Zh + j * 2 + 4) = (uint32_t)__bfloat16_as_ushort(h2) | ((uint32_t)__bfloat16_as_ushort(h3) << 16);
                        *(uint32_t*)(Zl + j * 2)     = (uint32_t)__bfloat16_as_ushort(l0) | ((uint32_t)__bfloat16_as_ushort(l1) << 16);
                        *(uint32_t*)(Zl + j * 2 + 4) = (uint32_t)__bfloat16_as_ushort(l2) | ((uint32_t)__bfloat16_as_ushort(l3) << 16);
                    }
                } else {
#pragma unroll
                    for (int j = 0; j < 32; j += 4) {
                        *(uint32_t*)(Zh + j * 2) = 0u; *(uint32_t*)(Zh + j * 2 + 4) = 0u;
                        *(uint32_t*)(Zl + j * 2) = 0u; *(uint32_t*)(Zl + j * 2 + 4) = 0u;
                    }
                }
            }
            __syncthreads();

            // ---- MMA over this chunk: 8 k-steps of 16 ----
            const uint32_t wkb = (uint32_t)(c * 256);   // byte offset into W2T k-dim
#pragma unroll 2
            for (int ks = 0; ks < 8; ks++) {
                const uint32_t akb = (uint32_t)(ks * 32);
                uint32_t ah[2][4], al[2][4];
                ldsm4(ah[0][0], ah[0][1], ah[0][2], ah[0][3], smb + ZH_OFF + aRow0 + akb);
                ldsm4(ah[1][0], ah[1][1], ah[1][2], ah[1][3], smb + ZH_OFF + aRow1 + akb);
                ldsm4(al[0][0], al[0][1], al[0][2], al[0][3], smb + ZL_OFF + aRow0 + akb);
                ldsm4(al[1][0], al[1][1], al[1][2], al[1][3], smb + ZL_OFF + aRow1 + akb);
                uint32_t bh[4][2], bl[4][2];
                ldsm4(bh[0][0], bh[0][1], bh[1][0], bh[1][1], smb + WH_OFF + bRow0 + wkb + akb);
                ldsm4(bh[2][0], bh[2][1], bh[3][0], bh[3][1], smb + WH_OFF + bRow1 + wkb + akb);
                ldsm4(bl[0][0], bl[0][1], bl[1][0], bl[1][1], smb + WL_OFF + bRow0 + wkb + akb);
                ldsm4(bl[2][0], bl[2][1], bl[3][0], bl[3][1], smb + WL_OFF + bRow1 + wkb + akb);
#pragma unroll
                for (int fm = 0; fm < 2; fm++)
#pragma unroll
                    for (int nf = 0; nf < 4; nf++) {
                        mma_bf16(cf[fm][nf], ah[fm][0], ah[fm][1], ah[fm][2], ah[fm][3], bh[nf][0], bh[nf][1]);
                        mma_bf16(cf[fm][nf], ah[fm][0], ah[fm][1], ah[fm][2], ah[fm][3], bl[nf][0], bl[nf][1]);
                        mma_bf16(cf[fm][nf], al[fm][0], al[fm][1], al[fm][2], al[fm][3], bh[nf][0], bh[nf][1]);
                    }
            }
            __syncthreads();   // Z chunk consumed; safe to overwrite
        }

        // ---- epilogue: atomics ----
        {
            const int g = lid >> 2, tg = lid & 3;
#pragma unroll
            for (int fm = 0; fm < 2; fm++) {
                const int row0 = m_base + fm * 16 + g;
                const int row1 = row0 + 8;
                const bool v0 = (base + row0) < N_EDGES;
                const bool v1 = (base + row1) < N_EDGES;
                const int d0 = s_dst[row0], d1 = s_dst[row1];
#pragma unroll
                for (int nf = 0; nf < 4; nf++) {
                    const int col = n0 + nf * 8 + tg * 2;
                    if (v0) {
                        float* p = g_acc + (size_t)d0 * 128 + col;
                        atomicAdd(p,     cf[fm][nf][0] + b2s[col]);
                        atomicAdd(p + 1, cf[fm][nf][1] + b2s[col + 1]);
                    }
                    if (v1) {
                        float* p = g_acc + (size_t)d1 * 128 + col;
                        atomicAdd(p,     cf[fm][nf][2] + b2s[col]);
                        atomicAdd(p + 1, cf[fm][nf][3] + b2s[col + 1]);
                    }
                }
            }
        }
        __syncthreads();   // s_dst reuse guard
    }
}

// ---------------- small elementwise kernels ----------------
__global__ void zero_kernel(float* p, int n) {
    int i = blockIdx.x * blockDim.x + threadIdx.x;
    if (i < n) p[i] = 0.f;
}
__global__ void gelu_kernel(const float* __restrict__ in, float* __restrict__ out, int n) {
    int i = blockIdx.x * blockDim.x + threadIdx.x;
    if (i < n) {
        float x = in[i];
        out[i] = 0.5f * x * (1.f + erff(x * 0.70710678118654752f));
    }
}
__global__ void scatter_kernel(const int* __restrict__ vg, const int* __restrict__ vs) {
    int i = blockIdx.x * blockDim.x + threadIdx.x;
    if (i >= N_MENTIONS * D) return;
    int m = i >> 7, c = i & 127;
    int v = vs[m], n = vg[m];
    atomicAdd(&g_vsum[v * D + c], g_h[n * D + c]);
    if (c == 0) atomicAdd(&g_vcnt[v], 1.0f);
}
__global__ void vrep_kernel() {
    int i = blockIdx.x * blockDim.x + threadIdx.x;
    if (i >= N_VARS * D) return;
    int v = i >> 7;
    g_vrep[i] = g_vsum[i] / fmaxf(g_vcnt[v], 1.0f);
}

// ---------------- host ----------------
static void launch_sgemm(const float* A, int lda, const float* B, int ldb, const float* bias,
                         float* C, int ldc, int M, int N, int K, int act)
{
    dim3 grid((N + 63) / 64, (M + 63) / 64);
    sgemm_kernel<<<grid, 256>>>(A, lda, B, ldb, bias, C, ldc, M, N, K, act);
}

extern "C" void kernel_launch(void* const* d_in, const int* in_sizes, int n_in,
                              void* d_out, int out_size)
{
    const float* node_labels = (const float*)d_in[0];
    const int*   edges       = (const int*)d_in[1];
    const int*   elab        = (const int*)d_in[2];
    const int*   vg          = (const int*)d_in[3];
    const int*   vs          = (const int*)d_in[4];
    int w = (n_in >= 20 && in_sizes[6] == 1) ? 7 : 6;
    const float* enc_W0  = (const float*)d_in[w + 0];
    const float* enc_b0  = (const float*)d_in[w + 1];
    const float* enc_W1  = (const float*)d_in[w + 2];
    const float* enc_b1  = (const float*)d_in[w + 3];
    const float* edge_emb= (const float*)d_in[w + 4];
    const float* mlp_W1  = (const float*)d_in[w + 5];
    const float* mlp_b1  = (const float*)d_in[w + 6];
    const float* mlp_W2  = (const float*)d_in[w + 7];
    const float* mlp_b2  = (const float*)d_in[w + 8];
    const float* dec_W0  = (const float*)d_in[w + 9];
    const float* dec_b0  = (const float*)d_in[w + 10];
    const float* dec_Wl  = (const float*)d_in[w + 11];
    const float* dec_bl  = (const float*)d_in[w + 12];
    float* out = (float*)d_out;

    float *h, *t, *acc, *PQ, *R, *vsum, *vcnt, *vrep;
    cudaGetSymbolAddress((void**)&h,    g_h);
    cudaGetSymbolAddress((void**)&t,    g_t);
    cudaGetSymbolAddress((void**)&acc,  g_acc);
    cudaGetSymbolAddress((void**)&PQ,   g_PQ);
    cudaGetSymbolAddress((void**)&R,    g_R);
    cudaGetSymbolAddress((void**)&vsum, g_vsum);
    cudaGetSymbolAddress((void**)&vcnt, g_vcnt);
    cudaGetSymbolAddress((void**)&vrep, g_vrep);

    int nsm = 148;
    cudaDeviceGetAttribute(&nsm, cudaDevAttrMultiProcessorCount, 0);

    cudaFuncSetAttribute(edge_kernel, cudaFuncAttributeMaxDynamicSharedMemorySize, EDGE_SMEM_BYTES);

    r_kernel<<<dim3(N_ETYPES, N_LAYERS), 256>>>(edge_emb, mlp_W1, mlp_b1, R);

    // encoder
    launch_sgemm(node_labels, IN_DIM, enc_W0, D, enc_b0, t, D, N_NODES, D, IN_DIM, 1);
    launch_sgemm(t, D, enc_W1, D, enc_b1, h, D, N_NODES, D, D, 0);

    for (int l = 0; l < N_LAYERS; l++) {
        const float* W1l = mlp_W1 + (size_t)l * 384 * 256;
        launch_sgemm(h, D, W1l,             256, nullptr, PQ,       512, N_NODES, 256, D, 0);
        launch_sgemm(h, D, W1l + 128 * 256, 256, nullptr, PQ + 256, 512, N_NODES, 256, D, 0);
        zero_kernel<<<(N_NODES * D + 255) / 256, 256>>>(acc, N_NODES * D);
        edge_kernel<<<nsm, 512, EDGE_SMEM_BYTES>>>(edges, elab,
                                                   R + (size_t)l * N_ETYPES * 256,
                                                   mlp_W2 + (size_t)l * 256 * 128,
                                                   mlp_b2 + (size_t)l * 128);
        gelu_kernel<<<(N_NODES * D + 255) / 256, 256>>>(acc, h, N_NODES * D);
    }

    // readout
    zero_kernel<<<(N_VARS * D + 255) / 256, 256>>>(vsum, N_VARS * D);
    zero_kernel<<<(N_VARS + 255) / 256, 256>>>(vcnt, N_VARS);
    scatter_kernel<<<(N_MENTIONS * D + 255) / 256, 256>>>(vg, vs);
    vrep_kernel<<<(N_VARS * D + 255) / 256, 256>>>();

    // decoder
    launch_sgemm(vrep, D, dec_W0, D, dec_b0, t, D, N_VARS, D, D, 1);
    launch_sgemm(t, D, dec_Wl, OUT_DIM, dec_bl, out, OUT_DIM, N_VARS, OUT_DIM, D, 0);
}

// round 8
// speedup vs baseline: 1.0634x; 1.0634x over previous
#include <cuda_runtime.h>
#include <cuda_bf16.h>
#include <math.h>
#include <stdint.h>

#define N_NODES   50000
#define N_EDGES   600000
#define IN_DIM    64
#define D         128
#define N_LAYERS  8
#define N_ETYPES  44
#define N_MENTIONS 100000
#define N_VARS    20000
#define OUT_DIM   100

// ---------------- scratch ----------------
__device__ float g_h[N_NODES * D];
__device__ float g_t[N_NODES * D];
__device__ float g_acc[N_NODES * D];
__device__ float g_PQ[N_NODES * 512];
__device__ float g_R[N_LAYERS * N_ETYPES * 256];
__device__ float g_vsum[N_VARS * D];
__device__ float g_vcnt[N_VARS];
__device__ float g_vrep[N_VARS * D];

// ---------------- helpers ----------------
__device__ __forceinline__ uint32_t smem_u32(const void* p) {
    uint32_t a;
    asm("{ .reg .u64 t; cvta.to.shared.u64 t, %1; cvt.u32.u64 %0, t; }" : "=r"(a) : "l"(p));
    return a;
}
__device__ __forceinline__ void ldsm4(uint32_t& r0, uint32_t& r1, uint32_t& r2, uint32_t& r3, uint32_t addr) {
    asm volatile("ldmatrix.sync.aligned.m8n8.x4.shared.b16 {%0,%1,%2,%3}, [%4];"
                 : "=r"(r0), "=r"(r1), "=r"(r2), "=r"(r3) : "r"(addr));
}
__device__ __forceinline__ void mma_bf16(float* c, const uint32_t* a, uint32_t b0, uint32_t b1) {
    asm volatile("mma.sync.aligned.m16n8k16.row.col.f32.bf16.bf16.f32 "
                 "{%0,%1,%2,%3}, {%4,%5,%6,%7}, {%8,%9}, {%0,%1,%2,%3};"
                 : "+f"(c[0]), "+f"(c[1]), "+f"(c[2]), "+f"(c[3])
                 : "r"(a[0]), "r"(a[1]), "r"(a[2]), "r"(a[3]), "r"(b0), "r"(b1));
}
__device__ __forceinline__ void red2(float* p, float x, float y) {
    asm volatile("red.global.add.v2.f32 [%0], {%1, %2};" :: "l"(p), "f"(x), "f"(y) : "memory");
}
__device__ __forceinline__ void bar_sync_512(int b)   { asm volatile("bar.sync %0, 512;"   :: "r"(b) : "memory"); }
__device__ __forceinline__ void bar_arrive_512(int b) { asm volatile("bar.arrive %0, 512;" :: "r"(b) : "memory"); }

// ---------------- tiled SGEMM 128x64, 8x4 micro ----------------
__global__ void sgemm_kernel(const float* __restrict__ A, int lda,
                             const float* __restrict__ B, int ldb,
                             const float* __restrict__ bias,
                             float* __restrict__ C, int ldc,
                             int M, int N, int K, int act)
{
    __shared__ __align__(16) float As[16][136];   // [k][m], 128 + pad
    __shared__ __align__(16) float Bs[16][64];    // [k][n]
    const int tid = threadIdx.x;
    const int m0 = blockIdx.y * 128, n0 = blockIdx.x * 64;
    const int ty = tid >> 4, tx = tid & 15;

    float acc[8][4];
#pragma unroll
    for (int i = 0; i < 8; i++)
#pragma unroll
        for (int j = 0; j < 4; j++) acc[i][j] = 0.f;

    for (int k0 = 0; k0 < K; k0 += 16) {
        {
            int r = tid >> 4, c = tid & 15;
#pragma unroll
            for (int p = 0; p < 8; p++) {
                int m = m0 + p * 16 + r;
                As[c][p * 16 + r] = (m < M) ? A[(size_t)m * lda + k0 + c] : 0.f;
            }
        }
        {
            int r = tid >> 6, c = tid & 63;
#pragma unroll
            for (int p = 0; p < 4; p++) {
                int k = k0 + p * 4 + r, n = n0 + c;
                Bs[p * 4 + r][c] = (n < N) ? B[(size_t)k * ldb + n] : 0.f;
            }
        }
        __syncthreads();
#pragma unroll
        for (int kk = 0; kk < 16; kk++) {
            float4 aA = *(const float4*)&As[kk][ty * 8];
            float4 aB = *(const float4*)&As[kk][ty * 8 + 4];
            float4 b4 = *(const float4*)&Bs[kk][tx * 4];
            float av[8] = {aA.x, aA.y, aA.z, aA.w, aB.x, aB.y, aB.z, aB.w};
#pragma unroll
            for (int i = 0; i < 8; i++) {
                acc[i][0] += av[i] * b4.x;
                acc[i][1] += av[i] * b4.y;
                acc[i][2] += av[i] * b4.z;
                acc[i][3] += av[i] * b4.w;
            }
        }
        __syncthreads();
    }
#pragma unroll
    for (int i = 0; i < 8; i++) {
        int m = m0 + ty * 8 + i;
        if (m >= M) continue;
#pragma unroll
        for (int j = 0; j < 4; j++) {
            int n = n0 + tx * 4 + j;
            if (n >= N) continue;
            float v = acc[i][j] + (bias ? bias[n] : 0.f);
            if (act == 1) v = fmaxf(v, 0.f);
            C[(size_t)m * ldc + n] = v;
        }
    }
}

// ---------------- per-etype R table ----------------
__global__ void r_kernel(const float* __restrict__ edge_emb,
                         const float* __restrict__ mlp_W1,
                         const float* __restrict__ mlp_b1,
                         float* __restrict__ R)
{
    int l = blockIdx.y, e = blockIdx.x, j = threadIdx.x;
    __shared__ float emb[128];
    if (j < 128) emb[j] = edge_emb[(l * N_ETYPES + e) * 128 + j];
    __syncthreads();
    const float* W = mlp_W1 + ((size_t)l * 384 + 256) * 256;
    float s = mlp_b1[l * 256 + j];
#pragma unroll 8
    for (int k = 0; k < 128; k++) s += emb[k] * W[k * 256 + j];
    R[((size_t)l * N_ETYPES + e) * 256 + j] = s;
}

// ---------------- warp-specialized mma.sync bf16x3 edge kernel ----------------
// 512 thr: warps 0-7 consumers (ldmatrix+MMA+red.v2), warps 8-15 producers (gather Z).
// Tile = 128 edges; K = 256 split in 4 chunks of 64, double-buffered in smem.
// Named barriers: FILL buf -> 1+buf, FREE buf -> 3+buf, IDXFREE parity -> 5+p, PRODSYNC -> 7.
#define WSTR   528
#define WH_OFF 0
#define WL_OFF 67584
#define ZOFF   135168
#define ZSTR   144
#define ZPLANE 18432
#define ZBUF   36864
#define EDGE_SMEM_BYTES 208896

__global__ __launch_bounds__(512, 1)
void edge_kernel(const int* __restrict__ edges,
                 const int* __restrict__ elab,
                 const float* __restrict__ Rl,    // [44][256]
                 const float* __restrict__ W2l,   // [256][128]
                 const float* __restrict__ b2l)   // [128]
{
    extern __shared__ __align__(16) char sm[];
    const uint32_t smb = smem_u32(sm);
    __shared__ int s_dst[2][128], s_src[2][128], s_lab[2][128];
    __shared__ float b2s[128];

    const int tid = threadIdx.x;
    const int wid = tid >> 5, lid = tid & 31;

    // stage W2^T hi/lo: row n (128 rows), k contiguous (256), stride 528B
    for (int i = tid; i < 256 * 128; i += 512) {
        int k = i >> 7, n = i & 127;
        float w = W2l[i];
        __nv_bfloat16 hb = __float2bfloat16_rn(w);
        __nv_bfloat16 lb = __float2bfloat16_rn(w - __bfloat162float(hb));
        *(unsigned short*)(sm + WH_OFF + n * WSTR + k * 2) = __bfloat16_as_ushort(hb);
        *(unsigned short*)(sm + WL_OFF + n * WSTR + k * 2) = __bfloat16_as_ushort(lb);
    }
    if (tid < 128) b2s[tid] = b2l[tid];
    __syncthreads();

    const int NT = (N_EDGES + 127) / 128;

    if (wid >= 8) {
        // ==================== PRODUCER ====================
        const int ptid = tid - 256;         // 0..255
        const int pe = ptid >> 1;           // edge row 0..127
        const int ph = ptid & 1;            // k-half within chunk (32 values)
        int iter = 0;
        for (int tile = blockIdx.x; tile < NT; tile += gridDim.x, iter++) {
            const int base = tile * 128;
            const int p = iter & 1;
            if (iter >= 2) bar_sync_512(5 + p);         // epilogue of tile-2 (same parity) done
            if (ptid < 128) {
                int eg = base + ptid;
                bool v = eg < N_EDGES;
                s_dst[p][ptid] = v ? edges[N_EDGES + eg] : 0;
                s_src[p][ptid] = v ? edges[eg] : 0;
                s_lab[p][ptid] = v ? elab[eg] : 0;
            }
            asm volatile("bar.sync 7, 256;" ::: "memory");   // producer-internal
            const bool ev = (base + pe) < N_EDGES;
            const int dn = s_dst[p][pe], sn = s_src[p][pe], lb = s_lab[p][pe];

            for (int c = 0; c < 4; c++) {
                const int kg = iter * 4 + c;
                const int buf = kg & 1;
                if (kg >= 2) bar_sync_512(3 + buf);     // buffer free
                char* Zh = sm + ZOFF + buf * ZBUF + pe * ZSTR + ph * 64;
                char* Zl = Zh + ZPLANE;
                if (ev) {
                    const int kc = c * 64 + ph * 32;
                    const float* Pp = g_PQ + (size_t)dn * 512 + kc;
                    const float* Qp = g_PQ + (size_t)sn * 512 + 256 + kc;
                    const float* Rp = Rl + lb * 256 + kc;
#pragma unroll
                    for (int j = 0; j < 32; j += 4) {
                        float4 p4 = *(const float4*)(Pp + j);
                        float4 q4 = *(const float4*)(Qp + j);
                        float4 r4 = *(const float4*)(Rp + j);
                        float z0 = fmaxf(p4.x + q4.x + r4.x, 0.f);
                        float z1 = fmaxf(p4.y + q4.y + r4.y, 0.f);
                        float z2 = fmaxf(p4.z + q4.z + r4.z, 0.f);
                        float z3 = fmaxf(p4.w + q4.w + r4.w, 0.f);
                        __nv_bfloat16 h0 = __float2bfloat16_rn(z0), h1 = __float2bfloat16_rn(z1);
                        __nv_bfloat16 h2 = __float2bfloat16_rn(z2), h3 = __float2bfloat16_rn(z3);
                        __nv_bfloat16 l0 = __float2bfloat16_rn(z0 - __bfloat162float(h0));
                        __nv_bfloat16 l1 = __float2bfloat16_rn(z1 - __bfloat162float(h1));
                        __nv_bfloat16 l2 = __float2bfloat16_rn(z2 - __bfloat162float(h2));
                        __nv_bfloat16 l3 = __float2bfloat16_rn(z3 - __bfloat162float(h3));
                        uint2 hv, lv;
                        hv.x = (uint32_t)__bfloat16_as_ushort(h0) | ((uint32_t)__bfloat16_as_ushort(h1) << 16);
                        hv.y = (uint32_t)__bfloat16_as_ushort(h2) | ((uint32_t)__bfloat16_as_ushort(h3) << 16);
                        lv.x = (uint32_t)__bfloat16_as_ushort(l0) | ((uint32_t)__bfloat16_as_ushort(l1) << 16);
                        lv.y = (uint32_t)__bfloat16_as_ushort(l2) | ((uint32_t)__bfloat16_as_ushort(l3) << 16);
                        *(uint2*)(Zh + j * 2) = hv;
                        *(uint2*)(Zl + j * 2) = lv;
                    }
                } else {
#pragma unroll
                    for (int j = 0; j < 32; j += 4) {
                        *(uint2*)(Zh + j * 2) = make_uint2(0u, 0u);
                        *(uint2*)(Zl + j * 2) = make_uint2(0u, 0u);
                    }
                }
                __threadfence_block();
                bar_arrive_512(1 + buf);                // buffer filled
            }
        }
    } else {
        // ==================== CONSUMER ====================
        const int mb = (wid & 3) * 32;
        const int nb = (wid >> 2) * 64;
        const uint32_t aR0 = (uint32_t)(mb + (lid & 15)) * ZSTR + ((lid & 16) ? 16u : 0u);
        const uint32_t aR1 = aR0 + 16u * ZSTR;
        const uint32_t bR0 = (uint32_t)(nb + (lid & 7) + ((lid & 16) ? 8 : 0)) * WSTR + ((lid & 8) ? 16u : 0u);
        const int g = lid >> 2, tg = lid & 3;

        int iter = 0;
        for (int tile = blockIdx.x; tile < NT; tile += gridDim.x, iter++) {
            const int base = tile * 128;
            const int p = iter & 1;

            float cf[2][8][4];
#pragma unroll
            for (int fm = 0; fm < 2; fm++)
#pragma unroll
                for (int nf = 0; nf < 8; nf++)
#pragma unroll
                    for (int r = 0; r < 4; r++) cf[fm][nf][r] = 0.f;

            for (int c = 0; c < 4; c++) {
                const int kg = iter * 4 + c;
                const int buf = kg & 1;
                bar_sync_512(1 + buf);                  // buffer filled
                const uint32_t zh = smb + ZOFF + buf * ZBUF;
                const uint32_t zl = zh + ZPLANE;
                const uint32_t wkb = (uint32_t)(c * 128);
#pragma unroll
                for (int ks = 0; ks < 4; ks++) {
                    const uint32_t akb = (uint32_t)(ks * 32);
                    uint32_t ah[4], a2h[4], al[4], a2l[4];
                    ldsm4(ah[0],  ah[1],  ah[2],  ah[3],  zh + aR0 + akb);
                    ldsm4(a2h[0], a2h[1], a2h[2], a2h[3], zh + aR1 + akb);
                    ldsm4(al[0],  al[1],  al[2],  al[3],  zl + aR0 + akb);
                    ldsm4(a2l[0], a2l[1], a2l[2], a2l[3], zl + aR1 + akb);
#pragma unroll
                    for (int nfp = 0; nfp < 4; nfp++) {
                        const uint32_t baddr = smb + WH_OFF + bR0 + (uint32_t)(nfp * 16 * WSTR) + wkb + akb;
                        uint32_t bh0, bh1, bh2, bh3, bl0, bl1, bl2, bl3;
                        ldsm4(bh0, bh1, bh2, bh3, baddr);
                        ldsm4(bl0, bl1, bl2, bl3, baddr + (uint32_t)(WL_OFF - WH_OFF));
                        float* c00 = cf[0][nfp * 2];
                        float* c01 = cf[0][nfp * 2 + 1];
                        float* c10 = cf[1][nfp * 2];
                        float* c11 = cf[1][nfp * 2 + 1];
                        mma_bf16(c00, ah, bh0, bh1);  mma_bf16(c00, ah, bl0, bl1);  mma_bf16(c00, al, bh0, bh1);
                        mma_bf16(c01, ah, bh2, bh3);  mma_bf16(c01, ah, bl2, bl3);  mma_bf16(c01, al, bh2, bh3);
                        mma_bf16(c10, a2h, bh0, bh1); mma_bf16(c10, a2h, bl0, bl1); mma_bf16(c10, a2l, bh0, bh1);
                        mma_bf16(c11, a2h, bh2, bh3); mma_bf16(c11, a2h, bl2, bl3); mma_bf16(c11, a2l, bh2, bh3);
                    }
                }
                bar_arrive_512(3 + buf);                // buffer free
            }

            // epilogue: red.v2 atomics
#pragma unroll
            for (int fm = 0; fm < 2; fm++) {
                const int row0 = mb + fm * 16 + g;
                const int row1 = row0 + 8;
                const bool v0 = (base + row0) < N_EDGES;
                const bool v1 = (base + row1) < N_EDGES;
                const int d0 = s_dst[p][row0], d1 = s_dst[p][row1];
#pragma unroll
                for (int nf = 0; nf < 8; nf++) {
                    const int col = nb + nf * 8 + tg * 2;
                    const float bb0 = b2s[col], bb1 = b2s[col + 1];
                    if (v0) red2(g_acc + (size_t)d0 * 128 + col, cf[fm][nf][0] + bb0, cf[fm][nf][1] + bb1);
                    if (v1) red2(g_acc + (size_t)d1 * 128 + col, cf[fm][nf][2] + bb0, cf[fm][nf][3] + bb1);
                }
            }
            bar_arrive_512(5 + p);                      // index buffer recyclable
        }
    }
}

// ---------------- small elementwise kernels ----------------
__global__ void zero_kernel(float* p, int n) {
    int i = blockIdx.x * blockDim.x + threadIdx.x;
    if (i < n) p[i] = 0.f;
}
__global__ void gelu_kernel(const float* __restrict__ in, float* __restrict__ out, int n) {
    int i = blockIdx.x * blockDim.x + threadIdx.x;
    if (i < n) {
        float x = in[i];
        out[i] = 0.5f * x * (1.f + erff(x * 0.70710678118654752f));
    }
}
__global__ void scatter_kernel(const int* __restrict__ vg, const int* __restrict__ vs) {
    int i = blockIdx.x * blockDim.x + threadIdx.x;
    if (i >= N_MENTIONS * D) return;
    int m = i >> 7, c = i & 127;
    int v = vs[m], n = vg[m];
    atomicAdd(&g_vsum[v * D + c], g_h[n * D + c]);
    if (c == 0) atomicAdd(&g_vcnt[v], 1.0f);
}
__global__ void vrep_kernel() {
    int i = blockIdx.x * blockDim.x + threadIdx.x;
    if (i >= N_VARS * D) return;
    int v = i >> 7;
    g_vrep[i] = g_vsum[i] / fmaxf(g_vcnt[v], 1.0f);
}

// ---------------- host ----------------
static void launch_sgemm(const float* A, int lda, const float* B, int ldb, const float* bias,
                         float* C, int ldc, int M, int N, int K, int act)
{
    dim3 grid((N + 63) / 64, (M + 127) / 128);
    sgemm_kernel<<<grid, 256>>>(A, lda, B, ldb, bias, C, ldc, M, N, K, act);
}

extern "C" void kernel_launch(void* const* d_in, const int* in_sizes, int n_in,
                              void* d_out, int out_size)
{
    const float* node_labels = (const float*)d_in[0];
    const int*   edges       = (const int*)d_in[1];
    const int*   elab        = (const int*)d_in[2];
    const int*   vg          = (const int*)d_in[3];
    const int*   vs          = (const int*)d_in[4];
    int w = (n_in >= 20 && in_sizes[6] == 1) ? 7 : 6;
    const float* enc_W0  = (const float*)d_in[w + 0];
    const float* enc_b0  = (const float*)d_in[w + 1];
    const float* enc_W1  = (const float*)d_in[w + 2];
    const float* enc_b1  = (const float*)d_in[w + 3];
    const float* edge_emb= (const float*)d_in[w + 4];
    const float* mlp_W1  = (const float*)d_in[w + 5];
    const float* mlp_b1  = (const float*)d_in[w + 6];
    const float* mlp_W2  = (const float*)d_in[w + 7];
    const float* mlp_b2  = (const float*)d_in[w + 8];
    const float* dec_W0  = (const float*)d_in[w + 9];
    const float* dec_b0  = (const float*)d_in[w + 10];
    const float* dec_Wl  = (const float*)d_in[w + 11];
    const float* dec_bl  = (const float*)d_in[w + 12];
    float* out = (float*)d_out;

    float *h, *t, *acc, *PQ, *R, *vsum, *vcnt, *vrep;
    cudaGetSymbolAddress((void**)&h,    g_h);
    cudaGetSymbolAddress((void**)&t,    g_t);
    cudaGetSymbolAddress((void**)&acc,  g_acc);
    cudaGetSymbolAddress((void**)&PQ,   g_PQ);
    cudaGetSymbolAddress((void**)&R,    g_R);
    cudaGetSymbolAddress((void**)&vsum, g_vsum);
    cudaGetSymbolAddress((void**)&vcnt, g_vcnt);
    cudaGetSymbolAddress((void**)&vrep, g_vrep);

    int nsm = 148;
    cudaDeviceGetAttribute(&nsm, cudaDevAttrMultiProcessorCount, 0);

    cudaFuncSetAttribute(edge_kernel, cudaFuncAttributeMaxDynamicSharedMemorySize, EDGE_SMEM_BYTES);

    r_kernel<<<dim3(N_ETYPES, N_LAYERS), 256>>>(edge_emb, mlp_W1, mlp_b1, R);

    // encoder
    launch_sgemm(node_labels, IN_DIM, enc_W0, D, enc_b0, t, D, N_NODES, D, IN_DIM, 1);
    launch_sgemm(t, D, enc_W1, D, enc_b1, h, D, N_NODES, D, D, 0);

    for (int l = 0; l < N_LAYERS; l++) {
        const float* W1l = mlp_W1 + (size_t)l * 384 * 256;
        launch_sgemm(h, D, W1l,             256, nullptr, PQ,       512, N_NODES, 256, D, 0);
        launch_sgemm(h, D, W1l + 128 * 256, 256, nullptr, PQ + 256, 512, N_NODES, 256, D, 0);
        zero_kernel<<<(N_NODES * D + 255) / 256, 256>>>(acc, N_NODES * D);
        edge_kernel<<<nsm, 512, EDGE_SMEM_BYTES>>>(edges, elab,
                                                   R + (size_t)l * N_ETYPES * 256,
                                                   mlp_W2 + (size_t)l * 256 * 128,
                                                   mlp_b2 + (size_t)l * 128);
        gelu_kernel<<<(N_NODES * D + 255) / 256, 256>>>(acc, h, N_NODES * D);
    }

    // readout
    zero_kernel<<<(N_VARS * D + 255) / 256, 256>>>(vsum, N_VARS * D);
    zero_kernel<<<(N_VARS + 255) / 256, 256>>>(vcnt, N_VARS);
    scatter_kernel<<<(N_MENTIONS * D + 255) / 256, 256>>>(vg, vs);
    vrep_kernel<<<(N_VARS * D + 255) / 256, 256>>>();

    // decoder
    launch_sgemm(vrep, D, dec_W0, D, dec_b0, t, D, N_VARS, D, D, 1);
    launch_sgemm(t, D, dec_Wl, OUT_DIM, dec_bl, out, OUT_DIM, N_VARS, OUT_DIM, D, 0);
}

// round 12
// speedup vs baseline: 3.2293x; 3.0369x over previous
#include <cuda_runtime.h>
#include <math.h>
#include <stdint.h>

#define N_NODES   50000
#define N_EDGES   600000
#define IN_DIM    64
#define D         128
#define N_LAYERS  8
#define N_ETYPES  44
#define N_MENTIONS 100000
#define N_VARS    20000
#define OUT_DIM   100

// ---------------- scratch ----------------
__device__ float g_h[N_NODES * D];
__device__ float g_t[N_NODES * D];
__device__ float g_PQ[N_NODES * 512];            // [n][0:256]=P(dst), [n][256:512]=Q(src)
__device__ float g_R[N_LAYERS * N_ETYPES * 256];
__device__ float g_S[N_NODES * 256];             // per-node Z sums
__device__ float g_vsum[N_VARS * D];
__device__ float g_vcnt[N_VARS];
__device__ float g_vrep[N_VARS * D];
// sort scratch
__device__ int   g_deg[N_NODES];
__device__ int   g_cur[N_NODES];
__device__ float g_degf[N_NODES];
__device__ int   g_part[256];
__device__ int   g_ssrc[N_EDGES];
__device__ int   g_sdst[N_EDGES];
__device__ int   g_slab[N_EDGES];

__device__ __forceinline__ void red2(float* p, float x, float y) {
    asm volatile("red.global.add.v2.f32 [%0], {%1, %2};" :: "l"(p), "f"(x), "f"(y) : "memory");
}

// ---------------- generic tiled SGEMM: C = act(A@B + rowscale[m]*bias[n]) ----------------
// act: 0=none, 1=relu, 2=gelu(exact erf). K multiple of 16.
__global__ void sgemm_kernel(const float* __restrict__ A, int lda,
                             const float* __restrict__ B, int ldb,
                             const float* __restrict__ bias,
                             const float* __restrict__ rowscale,
                             float* __restrict__ C, int ldc,
                             int M, int N, int K, int act)
{
    __shared__ __align__(16) float As[16][68];
    __shared__ __align__(16) float Bs[16][64];
    const int tid = threadIdx.x;
    const int m0 = blockIdx.y * 64, n0 = blockIdx.x * 64;
    const int ty = tid >> 4, tx = tid & 15;

    float acc[4][4];
#pragma unroll
    for (int i = 0; i < 4; i++)
#pragma unroll
        for (int j = 0; j < 4; j++) acc[i][j] = 0.f;

    for (int k0 = 0; k0 < K; k0 += 16) {
        {
            int r = tid >> 4, c = tid & 15;
#pragma unroll
            for (int p = 0; p < 4; p++) {
                int m = m0 + p * 16 + r;
                As[c][p * 16 + r] = (m < M) ? A[(size_t)m * lda + k0 + c] : 0.f;
            }
        }
        {
            int r = tid >> 6, c = tid & 63;
#pragma unroll
            for (int p = 0; p < 4; p++) {
                int k = k0 + p * 4 + r, n = n0 + c;
                Bs[p * 4 + r][c] = (n < N) ? B[(size_t)k * ldb + n] : 0.f;
            }
        }
        __syncthreads();
#pragma unroll
        for (int kk = 0; kk < 16; kk++) {
            float4 a4 = *(const float4*)&As[kk][ty * 4];
            float4 b4 = *(const float4*)&Bs[kk][tx * 4];
            acc[0][0] += a4.x * b4.x; acc[0][1] += a4.x * b4.y; acc[0][2] += a4.x * b4.z; acc[0][3] += a4.x * b4.w;
            acc[1][0] += a4.y * b4.x; acc[1][1] += a4.y * b4.y; acc[1][2] += a4.y * b4.z; acc[1][3] += a4.y * b4.w;
            acc[2][0] += a4.z * b4.x; acc[2][1] += a4.z * b4.y; acc[2][2] += a4.z * b4.z; acc[2][3] += a4.z * b4.w;
            acc[3][0] += a4.w * b4.x; acc[3][1] += a4.w * b4.y; acc[3][2] += a4.w * b4.z; acc[3][3] += a4.w * b4.w;
        }
        __syncthreads();
    }
#pragma unroll
    for (int i = 0; i < 4; i++) {
        int m = m0 + ty * 4 + i;
        if (m >= M) continue;
        float rs = rowscale ? rowscale[m] : 1.f;
#pragma unroll
        for (int j = 0; j < 4; j++) {
            int n = n0 + tx * 4 + j;
            if (n >= N) continue;
            float v = acc[i][j] + (bias ? rs * bias[n] : 0.f);
            if (act == 1) v = fmaxf(v, 0.f);
            else if (act == 2) v = 0.5f * v * (1.f + erff(v * 0.70710678118654752f));
            C[(size_t)m * ldc + n] = v;
        }
    }
}

// ---------------- per-etype R table ----------------
__global__ void r_kernel(const float* __restrict__ edge_emb,
                         const float* __restrict__ mlp_W1,
                         const float* __restrict__ mlp_b1,
                         float* __restrict__ R)
{
    int l = blockIdx.y, e = blockIdx.x, j = threadIdx.x;
    __shared__ float emb[128];
    if (j < 128) emb[j] = edge_emb[(l * N_ETYPES + e) * 128 + j];
    __syncthreads();
    const float* W = mlp_W1 + ((size_t)l * 384 + 256) * 256;
    float s = mlp_b1[l * 256 + j];
#pragma unroll 8
    for (int k = 0; k < 128; k++) s += emb[k] * W[k * 256 + j];
    R[((size_t)l * N_ETYPES + e) * 256 + j] = s;
}

// ---------------- counting sort by dst ----------------
__global__ void zero_int_kernel(int* p, int n) {
    int i = blockIdx.x * blockDim.x + threadIdx.x;
    if (i < n) p[i] = 0;
}
__global__ void hist_kernel(const int* __restrict__ edges) {
    int e = blockIdx.x * blockDim.x + threadIdx.x;
    if (e < N_EDGES) atomicAdd(&g_deg[edges[N_EDGES + e]], 1);
}
#define SCAN_B 512
__global__ void scan1_kernel() {   // per-block sums
    __shared__ int s[SCAN_B];
    int i = blockIdx.x * SCAN_B + threadIdx.x;
    s[threadIdx.x] = (i < N_NODES) ? g_deg[i] : 0;
    __syncthreads();
    for (int off = SCAN_B / 2; off > 0; off >>= 1) {
        if (threadIdx.x < off) s[threadIdx.x] += s[threadIdx.x + off];
        __syncthreads();
    }
    if (threadIdx.x == 0) g_part[blockIdx.x] = s[0];
}
__global__ void scan2_kernel(int nb) {  // exclusive scan of partials (1 block, serial per thread)
    __shared__ int s[256];
    s[threadIdx.x] = (threadIdx.x < nb) ? g_part[threadIdx.x] : 0;
    __syncthreads();
    if (threadIdx.x < nb) {
        int sum = 0;
        for (int j = 0; j < threadIdx.x; j++) sum += s[j];
        g_part[threadIdx.x] = sum;
    }
}
__global__ void scan3_kernel() {   // exclusive scan within block + offset -> g_cur, g_degf
    __shared__ int s[SCAN_B];
    int i = blockIdx.x * SCAN_B + threadIdx.x;
    int v = (i < N_NODES) ? g_deg[i] : 0;
    s[threadIdx.x] = v;
    __syncthreads();
    for (int o = 1; o < SCAN_B; o <<= 1) {
        int t = (threadIdx.x >= o) ? s[threadIdx.x - o] : 0;
        __syncthreads();
        s[threadIdx.x] += t;
        __syncthreads();
    }
    if (i < N_NODES) {
        int excl = s[threadIdx.x] - v + g_part[blockIdx.x];
        g_cur[i] = excl;
        g_degf[i] = (float)v;
    }
}
__global__ void sort_kernel(const int* __restrict__ edges, const int* __restrict__ elab) {
    int e = blockIdx.x * blockDim.x + threadIdx.x;
    if (e >= N_EDGES) return;
    int d = edges[N_EDGES + e];
    int p = atomicAdd(&g_cur[d], 1);
    g_ssrc[p] = edges[e];
    g_sdst[p] = d;
    g_slab[p] = elab[e];
}

// ---------------- edge pass: S[dst] += relu(P[dst]+Q[src]+R[lab]) ----------------
// edges sorted by dst; 1 warp owns a contiguous range, accumulates in regs, flushes on dst change.
#define EPB 1024
__global__ __launch_bounds__(256)
void edge_kernel(const float* __restrict__ Rl)
{
    const int w = threadIdx.x >> 5, lane = threadIdx.x & 31;
    int e0 = blockIdx.x * EPB + w * (EPB / 8);
    int e1 = e0 + (EPB / 8);
    if (e1 > N_EDGES) e1 = N_EDGES;
    if (e0 >= e1) return;
    const int l4 = lane * 4;

    float4 a0 = make_float4(0.f, 0.f, 0.f, 0.f);
    float4 a1 = make_float4(0.f, 0.f, 0.f, 0.f);
    int cur = g_sdst[e0];
    const float* Pb = g_PQ + (size_t)cur * 512;
    float4 P0 = *(const float4*)(Pb + l4);
    float4 P1 = *(const float4*)(Pb + 128 + l4);

    for (int e = e0; e < e1; ++e) {
        int d = g_sdst[e];
        if (d != cur) {
            float* S = g_S + (size_t)cur * 256 + l4;
            red2(S,       a0.x, a0.y); red2(S + 2,   a0.z, a0.w);
            red2(S + 128, a1.x, a1.y); red2(S + 130, a1.z, a1.w);
            a0 = make_float4(0.f, 0.f, 0.f, 0.f);
            a1 = make_float4(0.f, 0.f, 0.f, 0.f);
            cur = d;
            const float* Pn = g_PQ + (size_t)cur * 512;
            P0 = *(const float4*)(Pn + l4);
            P1 = *(const float4*)(Pn + 128 + l4);
        }
        int s = g_ssrc[e], lb = g_slab[e];
        const float* Q = g_PQ + (size_t)s * 512 + 256;
        float4 q0 = *(const float4*)(Q + l4);
        float4 q1 = *(const float4*)(Q + 128 + l4);
        const float* Rp = Rl + lb * 256;
        float4 r0 = *(const float4*)(Rp + l4);
        float4 r1 = *(const float4*)(Rp + 128 + l4);
        a0.x += fmaxf(P0.x + q0.x + r0.x, 0.f);
        a0.y += fmaxf(P0.y + q0.y + r0.y, 0.f);
        a0.z += fmaxf(P0.z + q0.z + r0.z, 0.f);
        a0.w += fmaxf(P0.w + q0.w + r0.w, 0.f);
        a1.x += fmaxf(P1.x + q1.x + r1.x, 0.f);
        a1.y += fmaxf(P1.y + q1.y + r1.y, 0.f);
        a1.z += fmaxf(P1.z + q1.z + r1.z, 0.f);
        a1.w += fmaxf(P1.w + q1.w + r1.w, 0.f);
    }
    float* S = g_S + (size_t)cur * 256 + l4;
    red2(S,       a0.x, a0.y); red2(S + 2,   a0.z, a0.w);
    red2(S + 128, a1.x, a1.y); red2(S + 130, a1.z, a1.w);
}

// ---------------- small elementwise kernels ----------------
__global__ void zero_kernel(float* p, int n) {
    int i = blockIdx.x * blockDim.x + threadIdx.x;
    if (i < n) p[i] = 0.f;
}
__global__ void scatter_kernel(const int* __restrict__ vg, const int* __restrict__ vs) {
    int i = blockIdx.x * blockDim.x + threadIdx.x;
    if (i >= N_MENTIONS * D) return;
    int m = i >> 7, c = i & 127;
    int v = vs[m], n = vg[m];
    atomicAdd(&g_vsum[v * D + c], g_h[n * D + c]);
    if (c == 0) atomicAdd(&g_vcnt[v], 1.0f);
}
__global__ void vrep_kernel() {
    int i = blockIdx.x * blockDim.x + threadIdx.x;
    if (i >= N_VARS * D) return;
    int v = i >> 7;
    g_vrep[i] = g_vsum[i] / fmaxf(g_vcnt[v], 1.0f);
}

// ---------------- host ----------------
static void launch_sgemm(const float* A, int lda, const float* B, int ldb, const float* bias,
                         const float* rowscale, float* C, int ldc, int M, int N, int K, int act)
{
    dim3 grid((N + 63) / 64, (M + 63) / 64);
    sgemm_kernel<<<grid, 256>>>(A, lda, B, ldb, bias, rowscale, C, ldc, M, N, K, act);
}

extern "C" void kernel_launch(void* const* d_in, const int* in_sizes, int n_in,
                              void* d_out, int out_size)
{
    const float* node_labels = (const float*)d_in[0];
    const int*   edges       = (const int*)d_in[1];
    const int*   elab        = (const int*)d_in[2];
    const int*   vg          = (const int*)d_in[3];
    const int*   vs          = (const int*)d_in[4];
    int w = (n_in >= 20 && in_sizes[6] == 1) ? 7 : 6;
    const float* enc_W0  = (const float*)d_in[w + 0];
    const float* enc_b0  = (const float*)d_in[w + 1];
    const float* enc_W1  = (const float*)d_in[w + 2];
    const float* enc_b1  = (const float*)d_in[w + 3];
    const float* edge_emb= (const float*)d_in[w + 4];
    const float* mlp_W1  = (const float*)d_in[w + 5];
    const float* mlp_b1  = (const float*)d_in[w + 6];
    const float* mlp_W2  = (const float*)d_in[w + 7];
    const float* mlp_b2  = (const float*)d_in[w + 8];
    const float* dec_W0  = (const float*)d_in[w + 9];
    const float* dec_b0  = (const float*)d_in[w + 10];
    const float* dec_Wl  = (const float*)d_in[w + 11];
    const float* dec_bl  = (const float*)d_in[w + 12];
    float* out = (float*)d_out;

    float *h, *t, *PQ, *R, *S, *vsum, *vcnt, *vrep, *degf;
    int *deg;
    cudaGetSymbolAddress((void**)&h,    g_h);
    cudaGetSymbolAddress((void**)&t,    g_t);
    cudaGetSymbolAddress((void**)&PQ,   g_PQ);
    cudaGetSymbolAddress((void**)&R,    g_R);
    cudaGetSymbolAddress((void**)&S,    g_S);
    cudaGetSymbolAddress((void**)&vsum, g_vsum);
    cudaGetSymbolAddress((void**)&vcnt, g_vcnt);
    cudaGetSymbolAddress((void**)&vrep, g_vrep);
    cudaGetSymbolAddress((void**)&degf, g_degf);
    cudaGetSymbolAddress((void**)&deg,  g_deg);

    const int NB = (N_NODES + SCAN_B - 1) / SCAN_B;   // 98

    // ---- counting sort of edges by dst (also produces deg) ----
    zero_int_kernel<<<(N_NODES + 255) / 256, 256>>>(deg, N_NODES);
    hist_kernel<<<(N_EDGES + 255) / 256, 256>>>(edges);
    scan1_kernel<<<NB, SCAN_B>>>();
    scan2_kernel<<<1, 256>>>(NB);
    scan3_kernel<<<NB, SCAN_B>>>();
    sort_kernel<<<(N_EDGES + 255) / 256, 256>>>(edges, elab);

    // ---- per-etype R tables ----
    r_kernel<<<dim3(N_ETYPES, N_LAYERS), 256>>>(edge_emb, mlp_W1, mlp_b1, R);

    // ---- encoder ----
    launch_sgemm(node_labels, IN_DIM, enc_W0, D, enc_b0, nullptr, t, D, N_NODES, D, IN_DIM, 1);
    launch_sgemm(t, D, enc_W1, D, enc_b1, nullptr, h, D, N_NODES, D, D, 0);

    // ---- GGNN layers ----
    for (int l = 0; l < N_LAYERS; l++) {
        const float* W1l = mlp_W1 + (size_t)l * 384 * 256;
        launch_sgemm(h, D, W1l,             256, nullptr, nullptr, PQ,       512, N_NODES, 256, D, 0);
        launch_sgemm(h, D, W1l + 128 * 256, 256, nullptr, nullptr, PQ + 256, 512, N_NODES, 256, D, 0);
        zero_kernel<<<(N_NODES * 256 + 255) / 256, 256>>>(S, N_NODES * 256);
        edge_kernel<<<(N_EDGES + EPB - 1) / EPB, 256>>>(R + (size_t)l * N_ETYPES * 256);
        // h = gelu(S @ W2 + deg * b2)
        launch_sgemm(S, 256, mlp_W2 + (size_t)l * 256 * 128, 128,
                     mlp_b2 + (size_t)l * 128, degf, h, D, N_NODES, 128, 256, 2);
    }

    // ---- readout ----
    zero_kernel<<<(N_VARS * D + 255) / 256, 256>>>(vsum, N_VARS * D);
    zero_kernel<<<(N_VARS + 255) / 256, 256>>>(vcnt, N_VARS);
    scatter_kernel<<<(N_MENTIONS * D + 255) / 256, 256>>>(vg, vs);
    vrep_kernel<<<(N_VARS * D + 255) / 256, 256>>>();

    // ---- decoder ----
    launch_sgemm(vrep, D, dec_W0, D, dec_b0, nullptr, t, D, N_VARS, D, D, 1);
    launch_sgemm(t, D, dec_Wl, OUT_DIM, dec_bl, nullptr, out, OUT_DIM, N_VARS, OUT_DIM, D, 0);
}